// round 4
// baseline (speedup 1.0000x reference)
#include <cuda_runtime.h>

#define K 7
#define HH 1024
#define WW 1024
#define NBINS (K * K)
#define TPB 256

// per-bin final scores (already divided by count and by K^2) + arrival counter
__device__ float g_score[64];          // 49 used, padded
__device__ unsigned int g_count;       // zero-init; reset by finalizer each run

__device__ __forceinline__ void bin_extents(float ci, float cj, float h, float w,
                                            int bi, int bj,
                                            int& r0, int& r1, int& c0, int& c1) {
    // Mirror the reference float32 arithmetic.
    float i0 = ci - h * 0.5f, i1 = ci + h * 0.5f;
    float j0 = cj - w * 0.5f, j1 = cj + w * 0.5f;
    float stepi = (i1 - i0) / (float)(K + 1);
    float stepj = (j1 - j0) / (float)(K + 1);
    float ic = i0 + (float)(bi + 1) * stepi;
    float jc = j0 + (float)(bj + 1) * stepj;
    float bh2 = h / (float)K * 0.5f;
    float bw2 = w / (float)K * 0.5f;
    r0 = (int)floorf((ic - bh2) * (float)HH);
    r1 = (int)ceilf ((ic + bh2) * (float)HH);
    c0 = (int)floorf((jc - bw2) * (float)WW);
    c1 = (int)ceilf ((jc + bw2) * (float)WW);
    r0 = max(r0, 0); r1 = min(r1, HH);
    c0 = max(c0, 0); c1 = min(c1, WW);
}

__global__ __launch_bounds__(TPB)
void psroi_fused_kernel(const float* __restrict__ x,
                        const float* __restrict__ region,
                        float* __restrict__ out) {
    const int bin = blockIdx.x;            // 0..48
    const int bi = bin / K, bj = bin % K;
    const int t  = threadIdx.x;

    const float ci = region[0], cj = region[1];
    const float rh = region[2], rw = region[3];

    int r0, r1, c0, c1;
    bin_extents(ci, cj, rh, rw, bi, bj, r0, r1, c0, c1);

    const int nrows = r1 - r0;
    const int ncols = c1 - c0;
    const float* __restrict__ chan = x + (size_t)bin * HH * WW;

    // coalesced grid-stride over the bin's pixels; all loads independent
    const int total = nrows * ncols;
    float acc = 0.0f;
    for (int idx = t; idx < total; idx += TPB) {
        int rr = idx / ncols;
        int cc = idx - rr * ncols;
        acc += __ldg(&chan[(size_t)(r0 + rr) * WW + (c0 + cc)]);
    }

    // deterministic block tree-reduction (256 -> 1)
    __shared__ float s[TPB];
    s[t] = acc;
    __syncthreads();
    #pragma unroll
    for (int o = TPB / 2; o > 0; o >>= 1) {
        if (t < o) s[t] += s[t + o];
        __syncthreads();
    }

    // publish this bin's FINAL score; last-arriving block does a tiny combine
    __shared__ bool is_last;
    if (t == 0) {
        g_score[bin] = s[0] / ((float)total * (float)NBINS);
        __threadfence();
        unsigned int prev = atomicAdd(&g_count, 1u);
        is_last = (prev == (unsigned int)(NBINS - 1));
    }
    __syncthreads();
    if (!is_last) return;

    // ---- tail: one coalesced 64-float read + tree reduce + store ----
    if (t < 64) {
        if (t == 0) __threadfence();          // acquire side
        __syncwarp();                          // (warp 0&1 cover t<64)
        float v = (t < NBINS) ? *(volatile float*)&g_score[t] : 0.0f;
        s[t] = v;
    }
    __syncthreads();
    if (t < 32) {
        s[t] += s[t + 32];
        __syncwarp();
        float v = s[t];
        #pragma unroll
        for (int o = 16; o > 0; o >>= 1)
            v += __shfl_down_sync(0xffffffffu, v, o);
        if (t == 0) {
            out[0] = v;
            __threadfence();
            g_count = 0;                       // reset for next graph replay
        }
    }
}

extern "C" void kernel_launch(void* const* d_in, const int* in_sizes, int n_in,
                              void* d_out, int out_size) {
    const float* x      = (const float*)d_in[0];
    const float* region = (const float*)d_in[1];
    float* out = (float*)d_out;

    psroi_fused_kernel<<<NBINS, TPB>>>(x, region, out);
}

// round 5
// speedup vs baseline: 1.0238x; 1.0238x over previous
#include <cuda_runtime.h>

#define K 7
#define HH 1024
#define WW 1024
#define NBINS (K * K)
#define TPB 256

// cross-block accumulator + arrival counter (zero-init; finalizer resets)
__device__ float        g_sum;
__device__ unsigned int g_count;

__device__ __forceinline__ void red_add_f32_gpu(float* addr, float v) {
    asm volatile("red.global.gpu.add.f32 [%0], %1;" :: "l"(addr), "f"(v) : "memory");
}
__device__ __forceinline__ unsigned int atom_add_acqrel_u32(unsigned int* addr, unsigned int v) {
    unsigned int old;
    asm volatile("atom.global.acq_rel.gpu.add.u32 %0, [%1], %2;"
                 : "=r"(old) : "l"(addr), "r"(v) : "memory");
    return old;
}
__device__ __forceinline__ float ld_acquire_f32(const float* addr) {
    float v;
    asm volatile("ld.global.acquire.gpu.f32 %0, [%1];" : "=f"(v) : "l"(addr) : "memory");
    return v;
}

__device__ __forceinline__ void bin_extents(float ci, float cj, float h, float w,
                                            int bi, int bj,
                                            int& r0, int& r1, int& c0, int& c1) {
    // Mirror the reference float32 arithmetic.
    float i0 = ci - h * 0.5f, i1 = ci + h * 0.5f;
    float j0 = cj - w * 0.5f, j1 = cj + w * 0.5f;
    float stepi = (i1 - i0) / (float)(K + 1);
    float stepj = (j1 - j0) / (float)(K + 1);
    float ic = i0 + (float)(bi + 1) * stepi;
    float jc = j0 + (float)(bj + 1) * stepj;
    float bh2 = h / (float)K * 0.5f;
    float bw2 = w / (float)K * 0.5f;
    r0 = (int)floorf((ic - bh2) * (float)HH);
    r1 = (int)ceilf ((ic + bh2) * (float)HH);
    c0 = (int)floorf((jc - bw2) * (float)WW);
    c1 = (int)ceilf ((jc + bw2) * (float)WW);
    r0 = max(r0, 0); r1 = min(r1, HH);
    c0 = max(c0, 0); c1 = min(c1, WW);
}

__global__ __launch_bounds__(TPB)
void psroi_fused_kernel(const float* __restrict__ x,
                        const float* __restrict__ region,
                        float* __restrict__ out) {
    const int bin  = blockIdx.x;           // 0..48
    const int bi   = bin / K, bj = bin % K;
    const int t    = threadIdx.x;
    const int wid  = t >> 5;
    const int lane = t & 31;

    // one LDG.128 for the whole region vector
    const float4 reg = *reinterpret_cast<const float4*>(region);

    int r0, r1, c0, c1;
    bin_extents(reg.x, reg.y, reg.z, reg.w, bi, bj, r0, r1, c0, c1);

    const int ncols = c1 - c0;
    const int total = (r1 - r0) * ncols;
    const float* __restrict__ chan = x + (size_t)bin * HH * WW;

    // warp-per-row, lane-per-column gather: no divisions, coalesced 128B rows
    float acc = 0.0f;
    for (int r = r0 + wid; r < r1; r += TPB / 32) {
        const float* __restrict__ rowp = chan + (size_t)r * WW;
        for (int c = c0 + lane; c < c1; c += 32)
            acc += __ldg(rowp + c);
    }

    // warp shuffle reduce (5 steps), then 8 leaders -> warp 0
    #pragma unroll
    for (int o = 16; o > 0; o >>= 1)
        acc += __shfl_down_sync(0xffffffffu, acc, o);

    __shared__ float s[TPB / 32];
    if (lane == 0) s[wid] = acc;
    __syncthreads();

    if (wid == 0) {
        float v = (lane < TPB / 32) ? s[lane] : 0.0f;
        #pragma unroll
        for (int o = 4; o > 0; o >>= 1)
            v += __shfl_down_sync(0xffffffffu, v, o);

        if (lane == 0) {
            // publish pre-divided bin score; release-ordered arrival
            red_add_f32_gpu(&g_sum, v / ((float)total * (float)NBINS));
            unsigned int prev = atom_add_acqrel_u32(&g_count, 1u);
            if (prev == (unsigned int)(NBINS - 1)) {
                // last block: all 49 reds visible (acquire). finalize + reset.
                out[0] = ld_acquire_f32(&g_sum);
                g_sum   = 0.0f;     // plain stores; kernel-end orders them
                g_count = 0u;       // ready for next graph replay
            }
        }
    }
}

extern "C" void kernel_launch(void* const* d_in, const int* in_sizes, int n_in,
                              void* d_out, int out_size) {
    const float* x      = (const float*)d_in[0];
    const float* region = (const float*)d_in[1];
    float* out = (float*)d_out;

    psroi_fused_kernel<<<NBINS, TPB>>>(x, region, out);
}